// round 5
// baseline (speedup 1.0000x reference)
#include <cuda_runtime.h>
#include <math.h>

// Problem constants (fixed by setup_inputs)
#define Bc 2
#define Vc 50000
#define Tc 3
#define Nc 32
#define Fc 128
#define Uc 128
#define Ec 300000
#define NV (Bc*Vc)          // 100000 vertices
#define SLOTS (Tc*Nc)       // 96 slots per vertex

typedef unsigned long long ull;

// Scratch (device globals; no allocation allowed)
__device__ float g_logits[Tc*Ec];
__device__ int   g_winner[NV*SLOTS];
__device__ float g_m[NV];
__device__ float g_c[NV];
__device__ float g_fdot[NV];
__device__ float g_wtilde[Tc*Fc];   // W_t @ W_att[128:]
__device__ float g_cterm[Tc];       // b_t · W_att[128:]

// ---------------------------------------------------------------------------
// K0: init winner grid to -1, out to 0 (vectorized)
// ---------------------------------------------------------------------------
__global__ void init_kernel(float4* __restrict__ out) {
    int i = blockIdx.x * 256 + threadIdx.x;
    if (i < NV*Uc/4)    out[i] = make_float4(0.f, 0.f, 0.f, 0.f);
    if (i < NV*SLOTS/4) ((int4*)g_winner)[i] = make_int4(-1, -1, -1, -1);
}

// ---------------------------------------------------------------------------
// K1: fdot[bv] = features[bv]·W_att[0:128] + b_att   (one warp per vertex)
// ---------------------------------------------------------------------------
__global__ void fdot_kernel(const float* __restrict__ feat,
                            const float* __restrict__ Wa,
                            const float* __restrict__ ba) {
    int w = (blockIdx.x * blockDim.x + threadIdx.x) >> 5;
    int lane = threadIdx.x & 31;
    if (w >= NV) return;
    const float4 f = ((const float4*)(feat + (size_t)w * Fc))[lane];
    const float4 a = __ldg(((const float4*)Wa) + lane);
    float s = f.x*a.x + f.y*a.y + f.z*a.z + f.w*a.w;
#pragma unroll
    for (int o = 16; o; o >>= 1)
        s += __shfl_xor_sync(0xffffffffu, s, o);
    if (lane == 0) g_fdot[w] = s + ba[0];
}

// ---------------------------------------------------------------------------
// K1b: w̃_t[f] = sum_u W_t[f,u]*Wa2[u],  cterm[t] = sum_u b_t[u]*Wa2[u]
// ---------------------------------------------------------------------------
__global__ void prep_kernel(const float* __restrict__ Wd,
                            const float* __restrict__ bd,
                            const float* __restrict__ Wa) {
    int t = blockIdx.x;
    int f = threadIdx.x;   // 128
    const float* row = Wd + ((size_t)t * 128 + f) * 128;
    float s = 0.f;
#pragma unroll 8
    for (int u = 0; u < 128; u++) s += row[u] * __ldg(&Wa[128 + u]);
    g_wtilde[t * 128 + f] = s;
    if (f == 0) {
        float cb = 0.f;
        for (int u = 0; u < 128; u++) cb += bd[t * 128 + u] * Wa[128 + u];
        g_cterm[t] = cb;
    }
}

// ---------------------------------------------------------------------------
// K2: logits via matrix-vector: logit = leaky(fdot[bv] + ef·w̃_t + cterm_t)
//     + last-write-wins winner scatter (atomicMax on edge id).
//     One warp per edge; memory bound on ef (460 MB).
// ---------------------------------------------------------------------------
__global__ void logits_kernel(const float* __restrict__ ef,
                              const int*   __restrict__ eidx) {
    int wg = (blockIdx.x * 256 + threadIdx.x) >> 5;
    int lane = threadIdx.x & 31;
    if (wg >= Tc * Ec) return;
    int t = wg / Ec;
    int e = wg - t * Ec;
    const float4 a = ((const float4*)(ef + ((size_t)t * Ec + e) * 128))[lane];
    const float4 w = __ldg(((const float4*)(g_wtilde + t * 128)) + lane);
    float s = a.x*w.x + a.y*w.y + a.z*w.z + a.w*w.w;
#pragma unroll
    for (int o = 16; o; o >>= 1)
        s += __shfl_xor_sync(0xffffffffu, s, o);
    if (lane == 0) {
        const int* ei = eidx + ((size_t)t * Ec + e) * 3;
        int b = ei[0], v = ei[1], sl = ei[2];
        int bv = b * Vc + v;
        float x = g_fdot[bv] + s + g_cterm[t];
        float logit = (x > 0.0f) ? x : 0.3f * x;
        g_logits[t * Ec + e] = logit;
        atomicMax(&g_winner[bv * SLOTS + t * Nc + sl], e);
    }
}

// ---------------------------------------------------------------------------
// K3: per-vertex softmax stats: m, c = degree/den.   One warp per vertex.
// ---------------------------------------------------------------------------
__global__ void vertex_kernel(const int* __restrict__ adj) {
    int vert = (blockIdx.x * blockDim.x + threadIdx.x) >> 5;
    int lane = threadIdx.x & 31;
    if (vert >= NV) return;
    const int base = vert * SLOTS;

    float l[3];
    int deg = 0;
#pragma unroll
    for (int i = 0; i < 3; i++) {
        int slot = i * 32 + lane;
        int w = g_winner[base + slot];
        deg += (adj[base + slot] >= 0) ? 1 : 0;
        l[i] = (w >= 0) ? g_logits[i * Ec + w] : -200.0f;
    }
    float m = fmaxf(fmaxf(l[0], l[1]), l[2]);
#pragma unroll
    for (int o = 16; o; o >>= 1)
        m = fmaxf(m, __shfl_xor_sync(0xffffffffu, m, o));
    float den = expf(l[0] - m) + expf(l[1] - m) + expf(l[2] - m);
#pragma unroll
    for (int o = 16; o; o >>= 1) {
        den += __shfl_xor_sync(0xffffffffu, den, o);
        deg += __shfl_xor_sync(0xffffffffu, deg, o);
    }
    if (lane == 0) {
        g_m[vert] = m;
        g_c[vert] = (float)deg / den;
    }
}

// ---------------------------------------------------------------------------
// K4: fused GEMM + weighted scatter.
//     xform = A @ W + b computed in registers (128x128 tile, 8x8 microtile,
//     packed f32x2 FMA); epilogue multiplies each row by att(e) and
//     atomic-adds float4s directly into out[bv]. No xform round-trip.
// ---------------------------------------------------------------------------
__global__ __launch_bounds__(256, 2)
void gemm_scatter_kernel(const float* __restrict__ ef,    // [T,E,128]
                         const float* __restrict__ Wd,    // [T,128,128]
                         const float* __restrict__ bd,    // [T,128]
                         const int*   __restrict__ eidx,  // [T,E,3]
                         float* __restrict__ out)
{
    __shared__ float sA[16][132];   // A chunk, transposed [k][row], padded
    __shared__ float sW[16][128];   // W chunk [k][u]
    __shared__ float satt[128];
    __shared__ int   sbv[128];

    const int t  = blockIdx.y;
    const int e0 = blockIdx.x * 128;
    const int rows = min(128, Ec - e0);
    const int tid = threadIdx.x;
    const int tx = tid & 15;        // 16 col-groups of 8
    const int ty = tid >> 4;        // 16 row-groups of 8

    const float* A = ef + ((size_t)t * Ec + e0) * 128;
    const float* W = Wd + (size_t)t * 128 * 128;

    // att per row while mainloop data is being staged (winner/logits/m/c ready)
    if (tid < rows) {
        int e = e0 + tid;
        const int* ei = eidx + ((size_t)t * Ec + e) * 3;
        int b = ei[0], v = ei[1], s = ei[2];
        int bv = b * Vc + v;
        int w = g_winner[bv * SLOTS + t * Nc + s];
        satt[tid] = expf(g_logits[t * Ec + w] - g_m[bv]) * g_c[bv];
        sbv[tid]  = bv;
    }

    ull acc[8][4];
#pragma unroll
    for (int i = 0; i < 8; i++)
#pragma unroll
        for (int j = 0; j < 4; j++) acc[i][j] = 0ull;

    for (int kc = 0; kc < 8; kc++) {
        const int kb = kc * 16;
        // load A chunk (transposed into sA[k][row])
        {
            int q = tid & 3;
            int r = tid >> 2;
#pragma unroll
            for (int it = 0; it < 2; it++) {
                int row = r + 64 * it;
                float4 v = make_float4(0.f, 0.f, 0.f, 0.f);
                if (row < rows)
                    v = *(const float4*)(A + (size_t)row * 128 + kb + q * 4);
                sA[q*4+0][row] = v.x;
                sA[q*4+1][row] = v.y;
                sA[q*4+2][row] = v.z;
                sA[q*4+3][row] = v.w;
            }
        }
        // load W chunk
        {
            int c4 = tid & 31;
            int kr = tid >> 5;
#pragma unroll
            for (int it = 0; it < 2; it++) {
                int k = kr + 8 * it;
                *(float4*)&sW[k][c4*4] = *(const float4*)(W + (size_t)(kb + k) * 128 + c4 * 4);
            }
        }
        __syncthreads();
#pragma unroll
        for (int k = 0; k < 16; k++) {
            float4 a0 = *(const float4*)&sA[k][ty*8];
            float4 a1 = *(const float4*)&sA[k][ty*8 + 4];
            ull w2[4];
#pragma unroll
            for (int j = 0; j < 4; j++)
                w2[j] = *(const ull*)&sW[k][tx*8 + 2*j];
            float av[8] = {a0.x, a0.y, a0.z, a0.w, a1.x, a1.y, a1.z, a1.w};
#pragma unroll
            for (int i = 0; i < 8; i++) {
                ull ad;
                asm("mov.b64 %0, {%1, %1};" : "=l"(ad) : "f"(av[i]));
#pragma unroll
                for (int j = 0; j < 4; j++)
                    asm("fma.rn.f32x2 %0, %1, %2, %0;" : "+l"(acc[i][j]) : "l"(ad), "l"(w2[j]));
            }
        }
        __syncthreads();
    }

    // epilogue: bias, att-weight, scatter-add
    float bias[8];
#pragma unroll
    for (int j = 0; j < 8; j++) bias[j] = bd[t*128 + tx*8 + j];

#pragma unroll
    for (int i = 0; i < 8; i++) {
        int r = ty*8 + i;
        if (r >= rows) break;
        float att = satt[r];
        int bv = sbv[r];
        float cc[8];
#pragma unroll
        for (int j = 0; j < 4; j++) {
            float lo, hi;
            asm("mov.b64 {%0, %1}, %2;" : "=f"(lo), "=f"(hi) : "l"(acc[i][j]));
            cc[2*j]   = (lo + bias[2*j])   * att;
            cc[2*j+1] = (hi + bias[2*j+1]) * att;
        }
        float4* dst = (float4*)(out + (size_t)bv * 128 + tx*8);
        atomicAdd(dst,     make_float4(cc[0], cc[1], cc[2], cc[3]));
        atomicAdd(dst + 1, make_float4(cc[4], cc[5], cc[6], cc[7]));
    }
}

// ---------------------------------------------------------------------------
extern "C" void kernel_launch(void* const* d_in, const int* in_sizes, int n_in,
                              void* d_out, int out_size) {
    const int*   adjacency  = (const int*)  d_in[0];
    const float* features   = (const float*)d_in[1];
    const int*   edge_idxs  = (const int*)  d_in[2];
    const float* edge_feats = (const float*)d_in[3];
    const float* W_dense    = (const float*)d_in[4];
    const float* b_dense    = (const float*)d_in[5];
    const float* W_att      = (const float*)d_in[6];
    const float* b_att      = (const float*)d_in[7];
    float* out = (float*)d_out;

    init_kernel<<<(NV*Uc/4 + 255)/256, 256>>>((float4*)out);
    fdot_kernel<<<(NV*32 + 255)/256, 256>>>(features, W_att, b_att);
    prep_kernel<<<Tc, 128>>>(W_dense, b_dense, W_att);
    logits_kernel<<<(Tc*Ec*32 + 255)/256, 256>>>(edge_feats, edge_idxs);
    vertex_kernel<<<(NV*32 + 255)/256, 256>>>(adjacency);
    dim3 gg((Ec + 127)/128, Tc);
    gemm_scatter_kernel<<<gg, 256>>>(edge_feats, W_dense, b_dense, edge_idxs, out);
}

// round 6
// speedup vs baseline: 1.0062x; 1.0062x over previous
#include <cuda_runtime.h>
#include <math.h>

// Problem constants (fixed by setup_inputs)
#define Bc 2
#define Vc 50000
#define Tc 3
#define Nc 32
#define Fc 128
#define Uc 128
#define Ec 300000
#define NV (Bc*Vc)          // 100000 vertices
#define SLOTS (Tc*Nc)       // 96 slots per vertex

typedef unsigned long long ull;

// Scratch (device globals; no allocation allowed)
__device__ float g_logits[Tc*Ec];
__device__ int   g_winner[NV*SLOTS];
__device__ float g_m[NV];
__device__ float g_c[NV];
__device__ float g_fdot[NV];
__device__ float g_wtilde[Tc*Fc];   // W_t @ W_att[128:]
__device__ float g_cterm[Tc];       // b_t · W_att[128:]

// ---------------------------------------------------------------------------
// K0: init winner grid to -1, out to 0 (vectorized)
// ---------------------------------------------------------------------------
__global__ void init_kernel(float4* __restrict__ out) {
    int i = blockIdx.x * 256 + threadIdx.x;
    if (i < NV*Uc/4)    out[i] = make_float4(0.f, 0.f, 0.f, 0.f);
    if (i < NV*SLOTS/4) ((int4*)g_winner)[i] = make_int4(-1, -1, -1, -1);
}

// ---------------------------------------------------------------------------
// K1: fdot[bv] = features[bv]·W_att[0:128] + b_att   (one warp per vertex)
// ---------------------------------------------------------------------------
__global__ void fdot_kernel(const float* __restrict__ feat,
                            const float* __restrict__ Wa,
                            const float* __restrict__ ba) {
    int w = (blockIdx.x * blockDim.x + threadIdx.x) >> 5;
    int lane = threadIdx.x & 31;
    if (w >= NV) return;
    const float4 f = ((const float4*)(feat + (size_t)w * Fc))[lane];
    const float4 a = __ldg(((const float4*)Wa) + lane);
    float s = f.x*a.x + f.y*a.y + f.z*a.z + f.w*a.w;
#pragma unroll
    for (int o = 16; o; o >>= 1)
        s += __shfl_xor_sync(0xffffffffu, s, o);
    if (lane == 0) g_fdot[w] = s + ba[0];
}

// ---------------------------------------------------------------------------
// K1b: w̃_t[f] = sum_u W_t[f,u]*Wa2[u],  cterm[t] = sum_u b_t[u]*Wa2[u]
// ---------------------------------------------------------------------------
__global__ void prep_kernel(const float* __restrict__ Wd,
                            const float* __restrict__ bd,
                            const float* __restrict__ Wa) {
    int t = blockIdx.x;
    int f = threadIdx.x;   // 128
    const float* row = Wd + ((size_t)t * 128 + f) * 128;
    float s = 0.f;
#pragma unroll 8
    for (int u = 0; u < 128; u++) s += row[u] * __ldg(&Wa[128 + u]);
    g_wtilde[t * 128 + f] = s;
    if (f == 0) {
        float cb = 0.f;
        for (int u = 0; u < 128; u++) cb += bd[t * 128 + u] * Wa[128 + u];
        g_cterm[t] = cb;
    }
}

// ---------------------------------------------------------------------------
// K2: logits via matrix-vector: logit = leaky(fdot[bv] + ef·w̃_t + cterm_t)
//     + last-write-wins winner scatter (atomicMax on edge id).
//     One warp per edge; memory bound on ef (460 MB).
// ---------------------------------------------------------------------------
__global__ void logits_kernel(const float* __restrict__ ef,
                              const int*   __restrict__ eidx) {
    int wg = (blockIdx.x * 256 + threadIdx.x) >> 5;
    int lane = threadIdx.x & 31;
    if (wg >= Tc * Ec) return;
    int t = wg / Ec;
    int e = wg - t * Ec;
    const float4 a = ((const float4*)(ef + ((size_t)t * Ec + e) * 128))[lane];
    const float4 w = __ldg(((const float4*)(g_wtilde + t * 128)) + lane);
    float s = a.x*w.x + a.y*w.y + a.z*w.z + a.w*w.w;
#pragma unroll
    for (int o = 16; o; o >>= 1)
        s += __shfl_xor_sync(0xffffffffu, s, o);
    if (lane == 0) {
        const int* ei = eidx + ((size_t)t * Ec + e) * 3;
        int b = ei[0], v = ei[1], sl = ei[2];
        int bv = b * Vc + v;
        float x = g_fdot[bv] + s + g_cterm[t];
        float logit = (x > 0.0f) ? x : 0.3f * x;
        g_logits[t * Ec + e] = logit;
        atomicMax(&g_winner[bv * SLOTS + t * Nc + sl], e);
    }
}

// ---------------------------------------------------------------------------
// K3: per-vertex softmax stats: m, c = degree/den.   One warp per vertex.
// ---------------------------------------------------------------------------
__global__ void vertex_kernel(const int* __restrict__ adj) {
    int vert = (blockIdx.x * blockDim.x + threadIdx.x) >> 5;
    int lane = threadIdx.x & 31;
    if (vert >= NV) return;
    const int base = vert * SLOTS;

    float l[3];
    int deg = 0;
#pragma unroll
    for (int i = 0; i < 3; i++) {
        int slot = i * 32 + lane;
        int w = g_winner[base + slot];
        deg += (adj[base + slot] >= 0) ? 1 : 0;
        l[i] = (w >= 0) ? g_logits[i * Ec + w] : -200.0f;
    }
    float m = fmaxf(fmaxf(l[0], l[1]), l[2]);
#pragma unroll
    for (int o = 16; o; o >>= 1)
        m = fmaxf(m, __shfl_xor_sync(0xffffffffu, m, o));
    float den = expf(l[0] - m) + expf(l[1] - m) + expf(l[2] - m);
#pragma unroll
    for (int o = 16; o; o >>= 1) {
        den += __shfl_xor_sync(0xffffffffu, den, o);
        deg += __shfl_xor_sync(0xffffffffu, deg, o);
    }
    if (lane == 0) {
        g_m[vert] = m;
        g_c[vert] = (float)deg / den;
    }
}

// ---------------------------------------------------------------------------
// K4: fused GEMM + weighted scatter.
//     xform = A @ W + b computed in registers (128x128 tile, 8x8 microtile,
//     packed f32x2 FMA); epilogue multiplies each row by att(e) and
//     atomic-adds float4s directly into out[bv]. No xform round-trip.
// ---------------------------------------------------------------------------
__global__ __launch_bounds__(256, 2)
void gemm_scatter_kernel(const float* __restrict__ ef,    // [T,E,128]
                         const float* __restrict__ Wd,    // [T,128,128]
                         const float* __restrict__ bd,    // [T,128]
                         const int*   __restrict__ eidx,  // [T,E,3]
                         float* __restrict__ out)
{
    __shared__ float sA[16][132];   // A chunk, transposed [k][row], padded
    __shared__ float sW[16][128];   // W chunk [k][u]
    __shared__ float satt[128];
    __shared__ int   sbv[128];

    const int t  = blockIdx.y;
    const int e0 = blockIdx.x * 128;
    const int rows = min(128, Ec - e0);
    const int tid = threadIdx.x;
    const int tx = tid & 15;        // 16 col-groups of 8
    const int ty = tid >> 4;        // 16 row-groups of 8

    const float* A = ef + ((size_t)t * Ec + e0) * 128;
    const float* W = Wd + (size_t)t * 128 * 128;

    // att per row while mainloop data is being staged (winner/logits/m/c ready)
    if (tid < rows) {
        int e = e0 + tid;
        const int* ei = eidx + ((size_t)t * Ec + e) * 3;
        int b = ei[0], v = ei[1], s = ei[2];
        int bv = b * Vc + v;
        int w = g_winner[bv * SLOTS + t * Nc + s];
        satt[tid] = expf(g_logits[t * Ec + w] - g_m[bv]) * g_c[bv];
        sbv[tid]  = bv;
    }

    ull acc[8][4];
#pragma unroll
    for (int i = 0; i < 8; i++)
#pragma unroll
        for (int j = 0; j < 4; j++) acc[i][j] = 0ull;

    for (int kc = 0; kc < 8; kc++) {
        const int kb = kc * 16;
        // load A chunk (transposed into sA[k][row])
        {
            int q = tid & 3;
            int r = tid >> 2;
#pragma unroll
            for (int it = 0; it < 2; it++) {
                int row = r + 64 * it;
                float4 v = make_float4(0.f, 0.f, 0.f, 0.f);
                if (row < rows)
                    v = *(const float4*)(A + (size_t)row * 128 + kb + q * 4);
                sA[q*4+0][row] = v.x;
                sA[q*4+1][row] = v.y;
                sA[q*4+2][row] = v.z;
                sA[q*4+3][row] = v.w;
            }
        }
        // load W chunk
        {
            int c4 = tid & 31;
            int kr = tid >> 5;
#pragma unroll
            for (int it = 0; it < 2; it++) {
                int k = kr + 8 * it;
                *(float4*)&sW[k][c4*4] = *(const float4*)(W + (size_t)(kb + k) * 128 + c4 * 4);
            }
        }
        __syncthreads();
#pragma unroll
        for (int k = 0; k < 16; k++) {
            float4 a0 = *(const float4*)&sA[k][ty*8];
            float4 a1 = *(const float4*)&sA[k][ty*8 + 4];
            ull w2[4];
#pragma unroll
            for (int j = 0; j < 4; j++)
                w2[j] = *(const ull*)&sW[k][tx*8 + 2*j];
            float av[8] = {a0.x, a0.y, a0.z, a0.w, a1.x, a1.y, a1.z, a1.w};
#pragma unroll
            for (int i = 0; i < 8; i++) {
                ull ad;
                asm("mov.b64 %0, {%1, %1};" : "=l"(ad) : "f"(av[i]));
#pragma unroll
                for (int j = 0; j < 4; j++)
                    asm("fma.rn.f32x2 %0, %1, %2, %0;" : "+l"(acc[i][j]) : "l"(ad), "l"(w2[j]));
            }
        }
        __syncthreads();
    }

    // epilogue: bias, att-weight, scatter-add
    float bias[8];
#pragma unroll
    for (int j = 0; j < 8; j++) bias[j] = bd[t*128 + tx*8 + j];

#pragma unroll
    for (int i = 0; i < 8; i++) {
        int r = ty*8 + i;
        if (r >= rows) break;
        float att = satt[r];
        int bv = sbv[r];
        float cc[8];
#pragma unroll
        for (int j = 0; j < 4; j++) {
            float lo, hi;
            asm("mov.b64 {%0, %1}, %2;" : "=f"(lo), "=f"(hi) : "l"(acc[i][j]));
            cc[2*j]   = (lo + bias[2*j])   * att;
            cc[2*j+1] = (hi + bias[2*j+1]) * att;
        }
        float4* dst = (float4*)(out + (size_t)bv * 128 + tx*8);
        atomicAdd(dst,     make_float4(cc[0], cc[1], cc[2], cc[3]));
        atomicAdd(dst + 1, make_float4(cc[4], cc[5], cc[6], cc[7]));
    }
}

// ---------------------------------------------------------------------------
extern "C" void kernel_launch(void* const* d_in, const int* in_sizes, int n_in,
                              void* d_out, int out_size) {
    const int*   adjacency  = (const int*)  d_in[0];
    const float* features   = (const float*)d_in[1];
    const int*   edge_idxs  = (const int*)  d_in[2];
    const float* edge_feats = (const float*)d_in[3];
    const float* W_dense    = (const float*)d_in[4];
    const float* b_dense    = (const float*)d_in[5];
    const float* W_att      = (const float*)d_in[6];
    const float* b_att      = (const float*)d_in[7];
    float* out = (float*)d_out;

    init_kernel<<<(NV*Uc/4 + 255)/256, 256>>>((float4*)out);
    fdot_kernel<<<(NV*32 + 255)/256, 256>>>(features, W_att, b_att);
    prep_kernel<<<Tc, 128>>>(W_dense, b_dense, W_att);
    logits_kernel<<<(Tc*Ec*32 + 255)/256, 256>>>(edge_feats, edge_idxs);
    vertex_kernel<<<(NV*32 + 255)/256, 256>>>(adjacency);
    dim3 gg((Ec + 127)/128, Tc);
    gemm_scatter_kernel<<<gg, 256>>>(edge_feats, W_dense, b_dense, edge_idxs, out);
}

// round 7
// speedup vs baseline: 1.0064x; 1.0002x over previous
#include <cuda_runtime.h>
#include <math.h>

// Problem constants (fixed by setup_inputs)
#define Bc 2
#define Vc 50000
#define Tc 3
#define Nc 32
#define Fc 128
#define Uc 128
#define Ec 300000
#define NV (Bc*Vc)          // 100000 vertices
#define SLOTS (Tc*Nc)       // 96 slots per vertex

typedef unsigned long long ull;

// Scratch (device globals; no allocation allowed)
__device__ float g_logits[Tc*Ec];
__device__ int   g_winner[NV*SLOTS];
__device__ float g_m[NV];
__device__ float g_c[NV];
__device__ float g_fdot[NV];
__device__ float g_wtilde[Tc*Fc];   // W_t @ W_att[128:]
__device__ float g_cterm[Tc];       // b_t · W_att[128:]

// ---------------------------------------------------------------------------
// K0: init winner grid to -1, out to 0 (vectorized)
// ---------------------------------------------------------------------------
__global__ void init_kernel(float4* __restrict__ out) {
    int i = blockIdx.x * 256 + threadIdx.x;
    if (i < NV*Uc/4)    out[i] = make_float4(0.f, 0.f, 0.f, 0.f);
    if (i < NV*SLOTS/4) ((int4*)g_winner)[i] = make_int4(-1, -1, -1, -1);
}

// ---------------------------------------------------------------------------
// K1: fdot[bv] = features[bv]·W_att[0:128] + b_att   (one warp per vertex)
// ---------------------------------------------------------------------------
__global__ void fdot_kernel(const float* __restrict__ feat,
                            const float* __restrict__ Wa,
                            const float* __restrict__ ba) {
    int w = (blockIdx.x * blockDim.x + threadIdx.x) >> 5;
    int lane = threadIdx.x & 31;
    if (w >= NV) return;
    const float4 f = ((const float4*)(feat + (size_t)w * Fc))[lane];
    const float4 a = __ldg(((const float4*)Wa) + lane);
    float s = f.x*a.x + f.y*a.y + f.z*a.z + f.w*a.w;
#pragma unroll
    for (int o = 16; o; o >>= 1)
        s += __shfl_xor_sync(0xffffffffu, s, o);
    if (lane == 0) g_fdot[w] = s + ba[0];
}

// ---------------------------------------------------------------------------
// K1b: w̃_t[f] = sum_u W_t[f,u]*Wa2[u],  cterm[t] = sum_u b_t[u]*Wa2[u]
// ---------------------------------------------------------------------------
__global__ void prep_kernel(const float* __restrict__ Wd,
                            const float* __restrict__ bd,
                            const float* __restrict__ Wa) {
    int t = blockIdx.x;
    int f = threadIdx.x;   // 128
    const float* row = Wd + ((size_t)t * 128 + f) * 128;
    float s = 0.f;
#pragma unroll 8
    for (int u = 0; u < 128; u++) s += row[u] * __ldg(&Wa[128 + u]);
    g_wtilde[t * 128 + f] = s;
    if (f == 0) {
        float cb = 0.f;
        for (int u = 0; u < 128; u++) cb += bd[t * 128 + u] * Wa[128 + u];
        g_cterm[t] = cb;
    }
}

// ---------------------------------------------------------------------------
// K2: logits via matrix-vector: logit = leaky(fdot[bv] + ef·w̃_t + cterm_t)
//     + last-write-wins winner scatter (atomicMax on edge id).
//     One warp per edge; memory bound on ef (460 MB).
// ---------------------------------------------------------------------------
__global__ void logits_kernel(const float* __restrict__ ef,
                              const int*   __restrict__ eidx) {
    int wg = (blockIdx.x * 256 + threadIdx.x) >> 5;
    int lane = threadIdx.x & 31;
    if (wg >= Tc * Ec) return;
    int t = wg / Ec;
    int e = wg - t * Ec;
    const float4 a = ((const float4*)(ef + ((size_t)t * Ec + e) * 128))[lane];
    const float4 w = __ldg(((const float4*)(g_wtilde + t * 128)) + lane);
    float s = a.x*w.x + a.y*w.y + a.z*w.z + a.w*w.w;
#pragma unroll
    for (int o = 16; o; o >>= 1)
        s += __shfl_xor_sync(0xffffffffu, s, o);
    if (lane == 0) {
        const int* ei = eidx + ((size_t)t * Ec + e) * 3;
        int b = ei[0], v = ei[1], sl = ei[2];
        int bv = b * Vc + v;
        float x = g_fdot[bv] + s + g_cterm[t];
        float logit = (x > 0.0f) ? x : 0.3f * x;
        g_logits[t * Ec + e] = logit;
        atomicMax(&g_winner[bv * SLOTS + t * Nc + sl], e);
    }
}

// ---------------------------------------------------------------------------
// K3: per-vertex softmax stats: m, c = degree/den.   One warp per vertex.
// ---------------------------------------------------------------------------
__global__ void vertex_kernel(const int* __restrict__ adj) {
    int vert = (blockIdx.x * blockDim.x + threadIdx.x) >> 5;
    int lane = threadIdx.x & 31;
    if (vert >= NV) return;
    const int base = vert * SLOTS;

    float l[3];
    int deg = 0;
#pragma unroll
    for (int i = 0; i < 3; i++) {
        int slot = i * 32 + lane;
        int w = g_winner[base + slot];
        deg += (adj[base + slot] >= 0) ? 1 : 0;
        l[i] = (w >= 0) ? g_logits[i * Ec + w] : -200.0f;
    }
    float m = fmaxf(fmaxf(l[0], l[1]), l[2]);
#pragma unroll
    for (int o = 16; o; o >>= 1)
        m = fmaxf(m, __shfl_xor_sync(0xffffffffu, m, o));
    float den = expf(l[0] - m) + expf(l[1] - m) + expf(l[2] - m);
#pragma unroll
    for (int o = 16; o; o >>= 1) {
        den += __shfl_xor_sync(0xffffffffu, den, o);
        deg += __shfl_xor_sync(0xffffffffu, deg, o);
    }
    if (lane == 0) {
        g_m[vert] = m;
        g_c[vert] = (float)deg / den;
    }
}

// ---------------------------------------------------------------------------
// K4: fused GEMM + weighted scatter.
//     xform = A @ W + b computed in registers (128x128 tile, 8x8 microtile,
//     packed f32x2 FMA); epilogue multiplies each row by att(e) and
//     atomic-adds float4s directly into out[bv]. No xform round-trip.
// ---------------------------------------------------------------------------
__global__ __launch_bounds__(256, 2)
void gemm_scatter_kernel(const float* __restrict__ ef,    // [T,E,128]
                         const float* __restrict__ Wd,    // [T,128,128]
                         const float* __restrict__ bd,    // [T,128]
                         const int*   __restrict__ eidx,  // [T,E,3]
                         float* __restrict__ out)
{
    __shared__ float sA[16][132];   // A chunk, transposed [k][row], padded
    __shared__ float sW[16][128];   // W chunk [k][u]
    __shared__ float satt[128];
    __shared__ int   sbv[128];

    const int t  = blockIdx.y;
    const int e0 = blockIdx.x * 128;
    const int rows = min(128, Ec - e0);
    const int tid = threadIdx.x;
    const int tx = tid & 15;        // 16 col-groups of 8
    const int ty = tid >> 4;        // 16 row-groups of 8

    const float* A = ef + ((size_t)t * Ec + e0) * 128;
    const float* W = Wd + (size_t)t * 128 * 128;

    // att per row while mainloop data is being staged (winner/logits/m/c ready)
    if (tid < rows) {
        int e = e0 + tid;
        const int* ei = eidx + ((size_t)t * Ec + e) * 3;
        int b = ei[0], v = ei[1], s = ei[2];
        int bv = b * Vc + v;
        int w = g_winner[bv * SLOTS + t * Nc + s];
        satt[tid] = expf(g_logits[t * Ec + w] - g_m[bv]) * g_c[bv];
        sbv[tid]  = bv;
    }

    ull acc[8][4];
#pragma unroll
    for (int i = 0; i < 8; i++)
#pragma unroll
        for (int j = 0; j < 4; j++) acc[i][j] = 0ull;

    for (int kc = 0; kc < 8; kc++) {
        const int kb = kc * 16;
        // load A chunk (transposed into sA[k][row])
        {
            int q = tid & 3;
            int r = tid >> 2;
#pragma unroll
            for (int it = 0; it < 2; it++) {
                int row = r + 64 * it;
                float4 v = make_float4(0.f, 0.f, 0.f, 0.f);
                if (row < rows)
                    v = *(const float4*)(A + (size_t)row * 128 + kb + q * 4);
                sA[q*4+0][row] = v.x;
                sA[q*4+1][row] = v.y;
                sA[q*4+2][row] = v.z;
                sA[q*4+3][row] = v.w;
            }
        }
        // load W chunk
        {
            int c4 = tid & 31;
            int kr = tid >> 5;
#pragma unroll
            for (int it = 0; it < 2; it++) {
                int k = kr + 8 * it;
                *(float4*)&sW[k][c4*4] = *(const float4*)(W + (size_t)(kb + k) * 128 + c4 * 4);
            }
        }
        __syncthreads();
#pragma unroll
        for (int k = 0; k < 16; k++) {
            float4 a0 = *(const float4*)&sA[k][ty*8];
            float4 a1 = *(const float4*)&sA[k][ty*8 + 4];
            ull w2[4];
#pragma unroll
            for (int j = 0; j < 4; j++)
                w2[j] = *(const ull*)&sW[k][tx*8 + 2*j];
            float av[8] = {a0.x, a0.y, a0.z, a0.w, a1.x, a1.y, a1.z, a1.w};
#pragma unroll
            for (int i = 0; i < 8; i++) {
                ull ad;
                asm("mov.b64 %0, {%1, %1};" : "=l"(ad) : "f"(av[i]));
#pragma unroll
                for (int j = 0; j < 4; j++)
                    asm("fma.rn.f32x2 %0, %1, %2, %0;" : "+l"(acc[i][j]) : "l"(ad), "l"(w2[j]));
            }
        }
        __syncthreads();
    }

    // epilogue: bias, att-weight, scatter-add
    float bias[8];
#pragma unroll
    for (int j = 0; j < 8; j++) bias[j] = bd[t*128 + tx*8 + j];

#pragma unroll
    for (int i = 0; i < 8; i++) {
        int r = ty*8 + i;
        if (r >= rows) break;
        float att = satt[r];
        int bv = sbv[r];
        float cc[8];
#pragma unroll
        for (int j = 0; j < 4; j++) {
            float lo, hi;
            asm("mov.b64 {%0, %1}, %2;" : "=f"(lo), "=f"(hi) : "l"(acc[i][j]));
            cc[2*j]   = (lo + bias[2*j])   * att;
            cc[2*j+1] = (hi + bias[2*j+1]) * att;
        }
        float4* dst = (float4*)(out + (size_t)bv * 128 + tx*8);
        atomicAdd(dst,     make_float4(cc[0], cc[1], cc[2], cc[3]));
        atomicAdd(dst + 1, make_float4(cc[4], cc[5], cc[6], cc[7]));
    }
}

// ---------------------------------------------------------------------------
extern "C" void kernel_launch(void* const* d_in, const int* in_sizes, int n_in,
                              void* d_out, int out_size) {
    const int*   adjacency  = (const int*)  d_in[0];
    const float* features   = (const float*)d_in[1];
    const int*   edge_idxs  = (const int*)  d_in[2];
    const float* edge_feats = (const float*)d_in[3];
    const float* W_dense    = (const float*)d_in[4];
    const float* b_dense    = (const float*)d_in[5];
    const float* W_att      = (const float*)d_in[6];
    const float* b_att      = (const float*)d_in[7];
    float* out = (float*)d_out;

    init_kernel<<<(NV*Uc/4 + 255)/256, 256>>>((float4*)out);
    fdot_kernel<<<(NV*32 + 255)/256, 256>>>(features, W_att, b_att);
    prep_kernel<<<Tc, 128>>>(W_dense, b_dense, W_att);
    logits_kernel<<<(Tc*Ec*32 + 255)/256, 256>>>(edge_feats, edge_idxs);
    vertex_kernel<<<(NV*32 + 255)/256, 256>>>(adjacency);
    dim3 gg((Ec + 127)/128, Tc);
    gemm_scatter_kernel<<<gg, 256>>>(edge_feats, W_dense, b_dense, edge_idxs, out);
}